// round 5
// baseline (speedup 1.0000x reference)
#include <cuda_runtime.h>
#include <cuda_fp16.h>
#include <mma.h>
#include <cstdint>

using namespace nvcuda;

#define NMAX 100000
#define EMAX 3200000

// Scratch (device globals -- no allocation allowed).
// g_cnt / g_cur are zero at module load and re-zeroed at the end of every
// call (tail of k_agg2_final), so each call sees them zeroed.
__device__ int     g_cnt[NMAX];
__device__ int     g_cur[NMAX];
__device__ float   g_dis[NMAX];
__device__ int     g_off[NMAX + 1];
__device__ int     g_csr_src[EMAX];
__device__ __align__(16) __half2 g_h1s[NMAX * 32];  // 64 cols fp16 per row
__device__ __align__(16) __half  g_h2s[NMAX * 32];  // 32 cols fp16 per row

// ---------------------------------------------------------------------------
__global__ void k_count(const int* __restrict__ dst, int E) {
    int e = blockIdx.x * blockDim.x + threadIdx.x;
    if (e < E) atomicAdd(&g_cnt[dst[e]], 1);
}

// Single-block full exclusive scan of g_cnt -> g_off, plus dis = rsqrt(cnt+1).
__global__ __launch_bounds__(1024) void k_scan_dis(int n) {
    __shared__ int s[1024];
    int t = threadIdx.x;
    int chunk = (n + 1023) / 1024;
    int b = t * chunk;
    int e = min(n, b + chunk);

    int sum = 0;
    for (int i = b; i < e; i++) sum += g_cnt[i];
    s[t] = sum;
    __syncthreads();
    for (int d = 1; d < 1024; d <<= 1) {
        int x = (t >= d) ? s[t - d] : 0;
        __syncthreads();
        s[t] += x;
        __syncthreads();
    }
    int run = s[t] - sum;  // exclusive prefix of this chunk
    for (int i = b; i < e; i++) {
        int v = g_cnt[i];
        g_off[i] = run;
        run += v;
        g_dis[i] = rsqrtf((float)(v + 1));
    }
    if (t == 1023) g_off[n] = run;
}

// ---------------------------------------------------------------------------
// Fused CSR fill + GEMM1 (wmma): h1s[32x64] = (x[32x128] @ W1) * dis (fp16)
#define XS_LD 136
#define W1_LD 72
__global__ __launch_bounds__(256) void k_gemm1_fill(
        const float* __restrict__ x, const float* __restrict__ W1,
        const int* __restrict__ src, const int* __restrict__ dst,
        int n, int E, int chunk) {
    __shared__ __align__(16) __half xs[32 * XS_LD];
    __shared__ __align__(16) __half w1s[128 * W1_LD];

    int t = threadIdx.x;
    int rowbase = blockIdx.x * 32;

    // CSR fill slice
    {
        int e0 = blockIdx.x * chunk;
        int e1 = min(E, e0 + chunk);
        for (int e = e0 + t; e < e1; e += 256) {
            int d = dst[e];
            int p = atomicAdd(&g_cur[d], 1);
            g_csr_src[g_off[d] + p] = src[e];
        }
    }

    // stage A (x tile) fp16
    for (int i = t; i < 1024; i += 256) {
        int r = i >> 5, c4 = i & 31;
        float4 v = reinterpret_cast<const float4*>(
            x + (size_t)(rowbase + r) * 128)[c4];
        __half2* p = reinterpret_cast<__half2*>(&xs[r * XS_LD + c4 * 4]);
        p[0] = __floats2half2_rn(v.x, v.y);
        p[1] = __floats2half2_rn(v.z, v.w);
    }
    // stage B (W1) fp16
    for (int i = t; i < 2048; i += 256) {
        int k = i >> 4, c4 = i & 15;
        float4 v = reinterpret_cast<const float4*>(W1)[k * 16 + c4];
        __half2* p = reinterpret_cast<__half2*>(&w1s[k * W1_LD + c4 * 4]);
        p[0] = __floats2half2_rn(v.x, v.y);
        p[1] = __floats2half2_rn(v.z, v.w);
    }
    __syncthreads();

    int w = t >> 5;
    int mrow = (w & 1) * 16;
    int ncol = (w >> 1) * 16;

    wmma::fragment<wmma::accumulator, 16, 16, 16, float> acc;
    wmma::fill_fragment(acc, 0.0f);
#pragma unroll
    for (int k0 = 0; k0 < 8; k0++) {
        wmma::fragment<wmma::matrix_a, 16, 16, 16, __half, wmma::row_major> fa;
        wmma::fragment<wmma::matrix_b, 16, 16, 16, __half, wmma::row_major> fb;
        wmma::load_matrix_sync(fa, &xs[mrow * XS_LD + k0 * 16], XS_LD);
        wmma::load_matrix_sync(fb, &w1s[(k0 * 16) * W1_LD + ncol], W1_LD);
        wmma::mma_sync(acc, fa, fb, acc);
    }
    __syncthreads();

    float* cs = reinterpret_cast<float*>(xs);
    wmma::store_matrix_sync(&cs[mrow * 64 + ncol], acc, 64, wmma::mem_row_major);
    __syncthreads();

    for (int i = t; i < 512; i += 256) {
        int r = i >> 4, c4 = i & 15;
        int gr = rowbase + r;
        float d = g_dis[gr];
        float4 v = reinterpret_cast<const float4*>(cs)[i];
        g_h1s[(size_t)gr * 32 + 2 * c4]     = __floats2half2_rn(v.x * d, v.y * d);
        g_h1s[(size_t)gr * 32 + 2 * c4 + 1] = __floats2half2_rn(v.z * d, v.w * d);
    }
}

// ---------------------------------------------------------------------------
// agg1 + relu + layer2 mini-GEMM. One warp per node.
// lane = (g = lane>>3: edge subgroup, c = lane&7: col chunk of 8 halves).
// Hot loop: 1 LDG.128 per lane per 4 edges, 2-way unrolled, no shfl.
__device__ __forceinline__ void acc8_add(float* acc, uint4 v) {
    const __half2* hv = reinterpret_cast<const __half2*>(&v);
    float2 f0 = __half22float2(hv[0]);
    float2 f1 = __half22float2(hv[1]);
    float2 f2 = __half22float2(hv[2]);
    float2 f3 = __half22float2(hv[3]);
    acc[0] += f0.x; acc[1] += f0.y;
    acc[2] += f1.x; acc[3] += f1.y;
    acc[4] += f2.x; acc[5] += f2.y;
    acc[6] += f3.x; acc[7] += f3.y;
}

__global__ __launch_bounds__(256) void k_agg1_l2(const float* __restrict__ b1,
                                                 const float* __restrict__ W2,
                                                 int n) {
    __shared__ float W2s[64 * 32];
    int t = threadIdx.x;
    for (int i = t; i < 512; i += 256)
        reinterpret_cast<float4*>(W2s)[i] = reinterpret_cast<const float4*>(W2)[i];
    __syncthreads();

    int warp = (blockIdx.x * blockDim.x + t) >> 5;
    if (warp >= n) return;
    int lane = t & 31;
    int g = lane >> 3;
    int c = lane & 7;
    int beg = g_off[warp], end = g_off[warp + 1];
    int deg = end - beg;

    float acc[8] = {0.f, 0.f, 0.f, 0.f, 0.f, 0.f, 0.f, 0.f};

    int nfull = deg & ~7;
    int e0 = beg;
    for (; e0 < beg + nfull; e0 += 8) {
        int sA = g_csr_src[e0 + g];
        int sB = g_csr_src[e0 + 4 + g];
        uint4 vA = *(reinterpret_cast<const uint4*>(g_h1s + (size_t)sA * 32) + c);
        uint4 vB = *(reinterpret_cast<const uint4*>(g_h1s + (size_t)sB * 32) + c);
        acc8_add(acc, vA);
        acc8_add(acc, vB);
    }
    for (; e0 < end; e0 += 4) {
        int ee = e0 + g;
        if (ee < end) {
            int s = g_csr_src[ee];
            uint4 v = *(reinterpret_cast<const uint4*>(g_h1s + (size_t)s * 32) + c);
            acc8_add(acc, v);
        }
    }

    // reduce across the 4 edge subgroups
#pragma unroll
    for (int r = 0; r < 8; r++) {
        acc[r] += __shfl_xor_sync(0xffffffffu, acc[r], 8);
        acc[r] += __shfl_xor_sync(0xffffffffu, acc[r], 16);
    }

    // epilogue: h = relu((agg + self)*dis + b1)  (lane holds cols 8c..8c+7)
    float di = g_dis[warp];
    float self[8] = {0.f, 0.f, 0.f, 0.f, 0.f, 0.f, 0.f, 0.f};
    {
        uint4 sv = *(reinterpret_cast<const uint4*>(g_h1s + (size_t)warp * 32) + c);
        acc8_add(self, sv);
    }
    float4 bA = reinterpret_cast<const float4*>(b1)[2 * c];
    float4 bB = reinterpret_cast<const float4*>(b1)[2 * c + 1];
    float bb[8] = {bA.x, bA.y, bA.z, bA.w, bB.x, bB.y, bB.z, bB.w};
    float h[8];
#pragma unroll
    for (int r = 0; r < 8; r++)
        h[r] = fmaxf((acc[r] + self[r]) * di + bb[r], 0.f);

    // mini-GEMM: out col = lane. Broadcast h[cc-chunk from lane cc].
    float o = 0.f;
#pragma unroll
    for (int cc = 0; cc < 8; cc++) {
#pragma unroll
        for (int r = 0; r < 8; r++) {
            float hv = __shfl_sync(0xffffffffu, h[r], cc);
            o += hv * W2s[(cc * 8 + r) * 32 + lane];
        }
    }
    g_h2s[(size_t)warp * 32 + lane] = __float2half_rn(o * di);
}

// ---------------------------------------------------------------------------
// agg2 + final FC. One warp per node. lane = (g = lane>>3, c = lane&7:
// cols 4c..4c+3, LDG.64). Tail: zero g_cnt/g_cur for the next call.
__device__ __forceinline__ void acc4_add(float* acc, uint2 v) {
    const __half2* hv = reinterpret_cast<const __half2*>(&v);
    float2 f0 = __half22float2(hv[0]);
    float2 f1 = __half22float2(hv[1]);
    acc[0] += f0.x; acc[1] += f0.y;
    acc[2] += f1.x; acc[3] += f1.y;
}

__global__ __launch_bounds__(256) void k_agg2_final(const float* __restrict__ b2,
                                                    const float* __restrict__ Wfc,
                                                    const float* __restrict__ bfc,
                                                    float* __restrict__ out, int n) {
    int tid = blockIdx.x * blockDim.x + threadIdx.x;
    int warp = tid >> 5;
    if (warp < n) {
        int lane = threadIdx.x & 31;
        int g = lane >> 3;
        int c = lane & 7;
        int beg = g_off[warp], end = g_off[warp + 1];
        int deg = end - beg;

        float acc[4] = {0.f, 0.f, 0.f, 0.f};
        int nfull = deg & ~7;
        int e0 = beg;
        for (; e0 < beg + nfull; e0 += 8) {
            int sA = g_csr_src[e0 + g];
            int sB = g_csr_src[e0 + 4 + g];
            uint2 vA = *(reinterpret_cast<const uint2*>(g_h2s + (size_t)sA * 32) + c);
            uint2 vB = *(reinterpret_cast<const uint2*>(g_h2s + (size_t)sB * 32) + c);
            acc4_add(acc, vA);
            acc4_add(acc, vB);
        }
        for (; e0 < end; e0 += 4) {
            int ee = e0 + g;
            if (ee < end) {
                int s = g_csr_src[ee];
                uint2 v = *(reinterpret_cast<const uint2*>(g_h2s + (size_t)s * 32) + c);
                acc4_add(acc, v);
            }
        }
#pragma unroll
        for (int r = 0; r < 4; r++) {
            acc[r] += __shfl_xor_sync(0xffffffffu, acc[r], 8);
            acc[r] += __shfl_xor_sync(0xffffffffu, acc[r], 16);
        }

        float di = g_dis[warp];
        float self[4] = {0.f, 0.f, 0.f, 0.f};
        {
            uint2 sv = *(reinterpret_cast<const uint2*>(g_h2s + (size_t)warp * 32) + c);
            acc4_add(self, sv);
        }
        float4 bv = reinterpret_cast<const float4*>(b2)[c];
        float4 wv = reinterpret_cast<const float4*>(Wfc)[c];
        float o = fmaxf((acc[0] + self[0]) * di + bv.x, 0.f) * wv.x
                + fmaxf((acc[1] + self[1]) * di + bv.y, 0.f) * wv.y
                + fmaxf((acc[2] + self[2]) * di + bv.z, 0.f) * wv.z
                + fmaxf((acc[3] + self[3]) * di + bv.w, 0.f) * wv.w;
        // sum over the 8 col chunks
        o += __shfl_xor_sync(0xffffffffu, o, 1);
        o += __shfl_xor_sync(0xffffffffu, o, 2);
        o += __shfl_xor_sync(0xffffffffu, o, 4);
        if (lane == 0) out[warp] = o + bfc[0];
    }
    // tail: re-zero counters for the next call (coalesced)
    if (tid < n) {
        g_cnt[tid] = 0;
        g_cur[tid] = 0;
    }
}

// ---------------------------------------------------------------------------
extern "C" void kernel_launch(void* const* d_in, const int* in_sizes, int n_in,
                              void* d_out, int out_size) {
    const float* x   = (const float*)d_in[0];
    const int*   ei  = (const int*)d_in[1];
    const float* W1  = (const float*)d_in[2];
    const float* b1  = (const float*)d_in[3];
    const float* W2  = (const float*)d_in[4];
    const float* b2  = (const float*)d_in[5];
    const float* Wfc = (const float*)d_in[6];
    const float* bfc = (const float*)d_in[7];
    float* out = (float*)d_out;

    int N = in_sizes[0] / 128;
    int E = in_sizes[1] / 2;
    const int* src = ei;
    const int* dst = ei + E;

    int rb32  = (N + 31) / 32;
    int eb256 = (E + 255) / 256;
    int chunk = (E + rb32 - 1) / rb32;

    k_count<<<eb256, 256>>>(dst, E);
    k_scan_dis<<<1, 1024>>>(N);
    k_gemm1_fill<<<rb32, 256>>>(x, W1, src, dst, N, E, chunk);
    k_agg1_l2<<<(N * 32 + 255) / 256, 256>>>(b1, W2, N);
    k_agg2_final<<<(N * 32 + 255) / 256, 256>>>(b2, Wfc, bfc, out, N);
}

// round 8
// speedup vs baseline: 1.8578x; 1.8578x over previous
#include <cuda_runtime.h>
#include <cuda_fp16.h>
#include <mma.h>
#include <cstdint>

using namespace nvcuda;

#define NMAX 100000
#define EMAX 3200000
#define SCAN_B 512

// Scratch (device globals -- no allocation allowed).
// g_cnt is zero at module load and re-zeroed at the end of every call
// (tail of k_agg2_final). g_cur is zeroed by k_scan3 each call.
__device__ int     g_cnt[NMAX];
__device__ int     g_cur[NMAX];
__device__ float   g_dis[NMAX];
__device__ int     g_off[NMAX + 1];
__device__ int     g_bsum[(NMAX + SCAN_B - 1) / SCAN_B];
__device__ int     g_boff[(NMAX + SCAN_B - 1) / SCAN_B];
__device__ int     g_csr_src[EMAX];
__device__ __align__(16) __half2 g_h1s[NMAX * 32];  // 64 cols fp16 per row
__device__ __align__(16) __half  g_h2s[NMAX * 32];  // 32 cols fp16 per row

// ---------------------------------------------------------------------------
__global__ void k_count(const int* __restrict__ dst, int E) {
    int e = blockIdx.x * blockDim.x + threadIdx.x;
    if (e < E) atomicAdd(&g_cnt[dst[e]], 1);
}

// ---- distributed coalesced scan of g_cnt into g_off -----------------------
__global__ __launch_bounds__(SCAN_B) void k_scan1(int n) {
    __shared__ int s[SCAN_B];
    int t = threadIdx.x;
    int i = blockIdx.x * SCAN_B + t;
    s[t] = (i < n) ? g_cnt[i] : 0;
    __syncthreads();
    for (int d = SCAN_B / 2; d > 0; d >>= 1) {
        if (t < d) s[t] += s[t + d];
        __syncthreads();
    }
    if (t == 0) g_bsum[blockIdx.x] = s[0];
}

__global__ __launch_bounds__(256) void k_scan2(int nb) {
    __shared__ int s[256];
    int t = threadIdx.x;
    int v = (t < nb) ? g_bsum[t] : 0;
    s[t] = v;
    __syncthreads();
    for (int d = 1; d < 256; d <<= 1) {
        int x = (t >= d) ? s[t - d] : 0;
        __syncthreads();
        s[t] += x;
        __syncthreads();
    }
    if (t < nb) g_boff[t] = s[t] - v;  // exclusive
}

// scan3 fused with dis computation + g_cur zeroing
__global__ __launch_bounds__(SCAN_B) void k_scan3(int n) {
    __shared__ int s[SCAN_B];
    int t = threadIdx.x;
    int i = blockIdx.x * SCAN_B + t;
    int v = (i < n) ? g_cnt[i] : 0;
    s[t] = v;
    __syncthreads();
    for (int d = 1; d < SCAN_B; d <<= 1) {
        int x = (t >= d) ? s[t - d] : 0;
        __syncthreads();
        s[t] += x;
        __syncthreads();
    }
    int incl = s[t] + g_boff[blockIdx.x];
    if (i < n) {
        g_off[i] = incl - v;
        if (i == n - 1) g_off[n] = incl;
        g_dis[i] = rsqrtf((float)(v + 1));
        g_cur[i] = 0;
    }
}

// ---------------------------------------------------------------------------
// Fused CSR fill + GEMM1 (wmma): h1s[32x64] = (x[32x128] @ W1) * dis (fp16)
#define XS_LD 136
#define W1_LD 72
__global__ __launch_bounds__(256) void k_gemm1_fill(
        const float* __restrict__ x, const float* __restrict__ W1,
        const int* __restrict__ src, const int* __restrict__ dst,
        int n, int E, int chunk) {
    __shared__ __align__(16) __half xs[32 * XS_LD];
    __shared__ __align__(16) __half w1s[128 * W1_LD];

    int t = threadIdx.x;
    int rowbase = blockIdx.x * 32;

    // CSR fill slice
    {
        int e0 = blockIdx.x * chunk;
        int e1 = min(E, e0 + chunk);
        for (int e = e0 + t; e < e1; e += 256) {
            int d = dst[e];
            int p = atomicAdd(&g_cur[d], 1);
            g_csr_src[g_off[d] + p] = src[e];
        }
    }

    // stage A (x tile) fp16
    for (int i = t; i < 1024; i += 256) {
        int r = i >> 5, c4 = i & 31;
        float4 v = reinterpret_cast<const float4*>(
            x + (size_t)(rowbase + r) * 128)[c4];
        __half2* p = reinterpret_cast<__half2*>(&xs[r * XS_LD + c4 * 4]);
        p[0] = __floats2half2_rn(v.x, v.y);
        p[1] = __floats2half2_rn(v.z, v.w);
    }
    // stage B (W1) fp16
    for (int i = t; i < 2048; i += 256) {
        int k = i >> 4, c4 = i & 15;
        float4 v = reinterpret_cast<const float4*>(W1)[k * 16 + c4];
        __half2* p = reinterpret_cast<__half2*>(&w1s[k * W1_LD + c4 * 4]);
        p[0] = __floats2half2_rn(v.x, v.y);
        p[1] = __floats2half2_rn(v.z, v.w);
    }
    __syncthreads();

    int w = t >> 5;
    int mrow = (w & 1) * 16;
    int ncol = (w >> 1) * 16;

    wmma::fragment<wmma::accumulator, 16, 16, 16, float> acc;
    wmma::fill_fragment(acc, 0.0f);
#pragma unroll
    for (int k0 = 0; k0 < 8; k0++) {
        wmma::fragment<wmma::matrix_a, 16, 16, 16, __half, wmma::row_major> fa;
        wmma::fragment<wmma::matrix_b, 16, 16, 16, __half, wmma::row_major> fb;
        wmma::load_matrix_sync(fa, &xs[mrow * XS_LD + k0 * 16], XS_LD);
        wmma::load_matrix_sync(fb, &w1s[(k0 * 16) * W1_LD + ncol], W1_LD);
        wmma::mma_sync(acc, fa, fb, acc);
    }
    __syncthreads();

    float* cs = reinterpret_cast<float*>(xs);
    wmma::store_matrix_sync(&cs[mrow * 64 + ncol], acc, 64, wmma::mem_row_major);
    __syncthreads();

    for (int i = t; i < 512; i += 256) {
        int r = i >> 4, c4 = i & 15;
        int gr = rowbase + r;
        float d = g_dis[gr];
        float4 v = reinterpret_cast<const float4*>(cs)[i];
        g_h1s[(size_t)gr * 32 + 2 * c4]     = __floats2half2_rn(v.x * d, v.y * d);
        g_h1s[(size_t)gr * 32 + 2 * c4 + 1] = __floats2half2_rn(v.z * d, v.w * d);
    }
}

// ---------------------------------------------------------------------------
__device__ __forceinline__ void acc8_add(float* acc, uint4 v) {
    const __half2* hv = reinterpret_cast<const __half2*>(&v);
    float2 f0 = __half22float2(hv[0]);
    float2 f1 = __half22float2(hv[1]);
    float2 f2 = __half22float2(hv[2]);
    float2 f3 = __half22float2(hv[3]);
    acc[0] += f0.x; acc[1] += f0.y;
    acc[2] += f1.x; acc[3] += f1.y;
    acc[4] += f2.x; acc[5] += f2.y;
    acc[6] += f3.x; acc[7] += f3.y;
}

// agg1 + relu + tensor-core layer2. 512 threads = 16 warps = 16 nodes/block.
// Per warp: wide-load gather (1 LDG.128 per lane / 4 edges, no shfl in loop),
// h row -> smem fp16; then 2 warps do [16x64]@[64x32] wmma (f32 accum).
#define HS_LD 72
#define W2_LD 40
__global__ __launch_bounds__(512) void k_agg1_l2(const float* __restrict__ b1,
                                                 const float* __restrict__ W2,
                                                 int n) {
    __shared__ __align__(16) __half hs[16 * HS_LD];
    __shared__ __align__(16) __half w2s[64 * W2_LD];
    __shared__ __align__(16) float  cs[16 * 32];

    int t = threadIdx.x;
    // stage W2 fp16 (64x32 = 512 float4)
    if (t < 512) {
        int k = t >> 3, c4 = t & 7;
        float4 v = reinterpret_cast<const float4*>(W2)[t];
        __half2* p = reinterpret_cast<__half2*>(&w2s[k * W2_LD + c4 * 4]);
        p[0] = __floats2half2_rn(v.x, v.y);
        p[1] = __floats2half2_rn(v.z, v.w);
    }

    int wid = t >> 5, lane = t & 31;
    int node = blockIdx.x * 16 + wid;
    int g = lane >> 3;
    int c = lane & 7;

    float h[8] = {0.f, 0.f, 0.f, 0.f, 0.f, 0.f, 0.f, 0.f};
    if (node < n) {
        int beg = g_off[node], end = g_off[node + 1];
        int deg = end - beg;

        float acc[8] = {0.f, 0.f, 0.f, 0.f, 0.f, 0.f, 0.f, 0.f};
        int nfull = deg & ~7;
        int e0 = beg;
        for (; e0 < beg + nfull; e0 += 8) {
            int sA = g_csr_src[e0 + g];
            int sB = g_csr_src[e0 + 4 + g];
            uint4 vA = *(reinterpret_cast<const uint4*>(g_h1s + (size_t)sA * 32) + c);
            uint4 vB = *(reinterpret_cast<const uint4*>(g_h1s + (size_t)sB * 32) + c);
            acc8_add(acc, vA);
            acc8_add(acc, vB);
        }
        for (; e0 < end; e0 += 4) {
            int ee = e0 + g;
            if (ee < end) {
                int s = g_csr_src[ee];
                uint4 v = *(reinterpret_cast<const uint4*>(g_h1s + (size_t)s * 32) + c);
                acc8_add(acc, v);
            }
        }
#pragma unroll
        for (int r = 0; r < 8; r++) {
            acc[r] += __shfl_xor_sync(0xffffffffu, acc[r], 8);
            acc[r] += __shfl_xor_sync(0xffffffffu, acc[r], 16);
        }

        float di = g_dis[node];
        float self[8] = {0.f, 0.f, 0.f, 0.f, 0.f, 0.f, 0.f, 0.f};
        {
            uint4 sv = *(reinterpret_cast<const uint4*>(g_h1s + (size_t)node * 32) + c);
            acc8_add(self, sv);
        }
        float4 bA = reinterpret_cast<const float4*>(b1)[2 * c];
        float4 bB = reinterpret_cast<const float4*>(b1)[2 * c + 1];
        float bb[8] = {bA.x, bA.y, bA.z, bA.w, bB.x, bB.y, bB.z, bB.w};
#pragma unroll
        for (int r = 0; r < 8; r++)
            h[r] = fmaxf((acc[r] + self[r]) * di + bb[r], 0.f);
    }
    // write h row to smem (g==0 lanes hold the full reduced values too)
    if (g == 0) {
        __half2* p = reinterpret_cast<__half2*>(&hs[wid * HS_LD + c * 8]);
        p[0] = __floats2half2_rn(h[0], h[1]);
        p[1] = __floats2half2_rn(h[2], h[3]);
        p[2] = __floats2half2_rn(h[4], h[5]);
        p[3] = __floats2half2_rn(h[6], h[7]);
    }
    __syncthreads();

    // layer2 GEMM: warps 0,1 compute C[16x32] = hs[16x64] @ w2s[64x32]
    if (wid < 2) {
        wmma::fragment<wmma::accumulator, 16, 16, 16, float> acc;
        wmma::fill_fragment(acc, 0.0f);
#pragma unroll
        for (int k0 = 0; k0 < 4; k0++) {
            wmma::fragment<wmma::matrix_a, 16, 16, 16, __half, wmma::row_major> fa;
            wmma::fragment<wmma::matrix_b, 16, 16, 16, __half, wmma::row_major> fb;
            wmma::load_matrix_sync(fa, &hs[k0 * 16], HS_LD);
            wmma::load_matrix_sync(fb, &w2s[(k0 * 16) * W2_LD + wid * 16], W2_LD);
            wmma::mma_sync(acc, fa, fb, acc);
        }
        wmma::store_matrix_sync(&cs[wid * 16], acc, 32, wmma::mem_row_major);
    }
    __syncthreads();

    // epilogue: h2s[node, col] = C * dis  (256 threads, half2 stores)
    if (t < 256) {
        int nd = t >> 4, c2 = t & 15;
        int gnode = blockIdx.x * 16 + nd;
        if (gnode < n) {
            float di = g_dis[gnode];
            float2 v = reinterpret_cast<const float2*>(cs)[nd * 16 + c2];
            reinterpret_cast<__half2*>(g_h2s)[(size_t)gnode * 16 + c2] =
                __floats2half2_rn(v.x * di, v.y * di);
        }
    }
}

// ---------------------------------------------------------------------------
__device__ __forceinline__ void acc4_add(float* acc, uint2 v) {
    const __half2* hv = reinterpret_cast<const __half2*>(&v);
    float2 f0 = __half22float2(hv[0]);
    float2 f1 = __half22float2(hv[1]);
    acc[0] += f0.x; acc[1] += f0.y;
    acc[2] += f1.x; acc[3] += f1.y;
}

// agg2 + final FC. One warp per node; wide loads. Tail: zero g_cnt.
__global__ __launch_bounds__(256) void k_agg2_final(const float* __restrict__ b2,
                                                    const float* __restrict__ Wfc,
                                                    const float* __restrict__ bfc,
                                                    float* __restrict__ out, int n) {
    int tid = blockIdx.x * blockDim.x + threadIdx.x;
    int warp = tid >> 5;
    if (warp < n) {
        int lane = threadIdx.x & 31;
        int g = lane >> 3;
        int c = lane & 7;
        int beg = g_off[warp], end = g_off[warp + 1];
        int deg = end - beg;

        float acc[4] = {0.f, 0.f, 0.f, 0.f};
        int nfull = deg & ~7;
        int e0 = beg;
        for (; e0 < beg + nfull; e0 += 8) {
            int sA = g_csr_src[e0 + g];
            int sB = g_csr_src[e0 + 4 + g];
            uint2 vA = *(reinterpret_cast<const uint2*>(g_h2s + (size_t)sA * 32) + c);
            uint2 vB = *(reinterpret_cast<const uint2*>(g_h2s + (size_t)sB * 32) + c);
            acc4_add(acc, vA);
            acc4_add(acc, vB);
        }
        for (; e0 < end; e0 += 4) {
            int ee = e0 + g;
            if (ee < end) {
                int s = g_csr_src[ee];
                uint2 v = *(reinterpret_cast<const uint2*>(g_h2s + (size_t)s * 32) + c);
                acc4_add(acc, v);
            }
        }
#pragma unroll
        for (int r = 0; r < 4; r++) {
            acc[r] += __shfl_xor_sync(0xffffffffu, acc[r], 8);
            acc[r] += __shfl_xor_sync(0xffffffffu, acc[r], 16);
        }

        float di = g_dis[warp];
        float self[4] = {0.f, 0.f, 0.f, 0.f};
        {
            uint2 sv = *(reinterpret_cast<const uint2*>(g_h2s + (size_t)warp * 32) + c);
            acc4_add(self, sv);
        }
        float4 bv = reinterpret_cast<const float4*>(b2)[c];
        float4 wv = reinterpret_cast<const float4*>(Wfc)[c];
        float o = fmaxf((acc[0] + self[0]) * di + bv.x, 0.f) * wv.x
                + fmaxf((acc[1] + self[1]) * di + bv.y, 0.f) * wv.y
                + fmaxf((acc[2] + self[2]) * di + bv.z, 0.f) * wv.z
                + fmaxf((acc[3] + self[3]) * di + bv.w, 0.f) * wv.w;
        o += __shfl_xor_sync(0xffffffffu, o, 1);
        o += __shfl_xor_sync(0xffffffffu, o, 2);
        o += __shfl_xor_sync(0xffffffffu, o, 4);
        if (lane == 0) out[warp] = o + bfc[0];
    }
    // tail: re-zero degree counters for the next call (coalesced)
    if (tid < n) g_cnt[tid] = 0;
}

// ---------------------------------------------------------------------------
extern "C" void kernel_launch(void* const* d_in, const int* in_sizes, int n_in,
                              void* d_out, int out_size) {
    const float* x   = (const float*)d_in[0];
    const int*   ei  = (const int*)d_in[1];
    const float* W1  = (const float*)d_in[2];
    const float* b1  = (const float*)d_in[3];
    const float* W2  = (const float*)d_in[4];
    const float* b2  = (const float*)d_in[5];
    const float* Wfc = (const float*)d_in[6];
    const float* bfc = (const float*)d_in[7];
    float* out = (float*)d_out;

    int N = in_sizes[0] / 128;
    int E = in_sizes[1] / 2;
    const int* src = ei;
    const int* dst = ei + E;

    int rb32  = (N + 31) / 32;
    int eb256 = (E + 255) / 256;
    int nscan = (N + SCAN_B - 1) / SCAN_B;
    int chunk = (E + rb32 - 1) / rb32;

    k_count<<<eb256, 256>>>(dst, E);
    k_scan1<<<nscan, SCAN_B>>>(N);
    k_scan2<<<1, 256>>>(nscan);
    k_scan3<<<nscan, SCAN_B>>>(N);
    k_gemm1_fill<<<rb32, 256>>>(x, W1, src, dst, N, E, chunk);
    k_agg1_l2<<<(N + 15) / 16, 512>>>(b1, W2, N);
    k_agg2_final<<<(N * 32 + 255) / 256, 256>>>(b2, Wfc, bfc, out, N);
}